// round 16
// baseline (speedup 1.0000x reference)
#include <cuda_runtime.h>
#include <cuda_bf16.h>
#include <cstdint>

#define N 4096
#define D 512
#define LA (-8.317766166719344f)
#define LB (-8.317766166719344f)
#define THRESH (-25.0f)
#define THRESH_P (-40.0f)
#define RPB 4
#define CAP 320
#define PBLK 256

/* ---- scratch (device globals) ---- */
__device__ __nv_bfloat162 d_S [(size_t)N * N / 2];
__device__ __nv_bfloat162 d_St[(size_t)N * N / 2];
__device__ __nv_bfloat16 d_Xb[(size_t)N * D];
__device__ __nv_bfloat16 d_Yb[(size_t)N * D];
__device__ float d_fh[N];
__device__ float d_gh[N];
__device__ float d_x2[N];
__device__ float d_y2[N];
__device__ float d_mf[N];
__device__ float d_mg[N];
__device__ float d_R[N];
__device__ float d_C[N];
__device__ unsigned short d_idxf[(size_t)N * CAP];
__device__ unsigned short d_idxg[(size_t)N * CAP];
__device__ int d_cntf[N];
__device__ int d_cntg[N];
/* two-level grid barrier state */
__device__ unsigned d_bkt[16];
__device__ unsigned d_master;
__device__ volatile unsigned d_gen;

__device__ __forceinline__ uint32_t smem_u32(const void* p) {
    uint32_t a;
    asm("{ .reg .u64 t; cvta.to.shared.u64 t, %1; cvt.u32.u64 %0, t; }"
        : "=r"(a) : "l"(p));
    return a;
}
__device__ __forceinline__ float bf16_raw_to_f(unsigned short s) {
    return __uint_as_float((unsigned)s << 16);
}
__device__ __forceinline__ void bar_reset(int tid, int bid) {
    if (bid == 0 && tid == 0) {
        for (int i = 0; i < 16; ++i) d_bkt[i] = 0;
        d_master = 0;
        d_gen = 0;
    }
}

/* ================= prep ================= */
__global__ void __launch_bounds__(256) prep_kernel(const float* __restrict__ x,
                                                   const float* __restrict__ y) {
    bar_reset(threadIdx.x, blockIdx.x);
    int warp = threadIdx.x >> 5, lane = threadIdx.x & 31;
    int id = blockIdx.x * 8 + warp;
    const float* src = (id < N) ? x : y;
    __nv_bfloat16* dstb = (id < N) ? d_Xb : d_Yb;
    int row = (id < N) ? id : id - N;
    const float4* p = (const float4*)(src + (size_t)row * D);
    float s = 0.f;
#pragma unroll
    for (int k = 0; k < 4; ++k) {
        float4 v = p[lane + 32 * k];
        s += v.x * v.x + v.y * v.y + v.z * v.z + v.w * v.w;
        __nv_bfloat162 b0 = __floats2bfloat162_rn(v.x, v.y);
        __nv_bfloat162 b1 = __floats2bfloat162_rn(v.z, v.w);
        uint2 u = make_uint2(*(unsigned*)&b0, *(unsigned*)&b1);
        *(uint2*)(dstb + (size_t)row * D + (lane + 32 * k) * 4) = u;
    }
#pragma unroll
    for (int o = 16; o; o >>= 1) s += __shfl_xor_sync(0xffffffffu, s, o);
    if (lane == 0) {
        if (id < N) { d_x2[row] = s; d_fh[row] = -s; }
        else        { d_y2[row] = s; d_gh[row] = -s; }
    }
}

/* ============ tensor-core GEMM: S = 2 X Y^T (bf16), also writes S^T ======== */
#define BK 64
__global__ void __launch_bounds__(256) gemm_tc_kernel() {
    __shared__ __align__(16) char smem_raw[128 * 136 * 2];
    __nv_bfloat16* As = (__nv_bfloat16*)smem_raw;
    __nv_bfloat16* Bs = As + 128 * BK;
    __nv_bfloat16* Ct = (__nv_bfloat16*)smem_raw;

    int tid = threadIdx.x;
    int warp = tid >> 5, lane = tid & 31;
    int wm = warp >> 2, wn = warp & 3;
    int bm = blockIdx.y * 128, bn = blockIdx.x * 128;

    float acc[4][4][4];
#pragma unroll
    for (int mi = 0; mi < 4; ++mi)
#pragma unroll
        for (int ni = 0; ni < 4; ++ni)
#pragma unroll
            for (int k = 0; k < 4; ++k) acc[mi][ni][k] = 0.f;

    uint32_t baseA = smem_u32(As), baseB = smem_u32(Bs);

    for (int k0 = 0; k0 < D; k0 += BK) {
        uint4* Av = (uint4*)As;
        uint4* Bv = (uint4*)Bs;
#pragma unroll
        for (int l = 0; l < 4; ++l) {
            int u = tid + l * 256;
            int r = u >> 3, c = u & 7;
            int pc = c ^ (r & 7);
            Av[r * 8 + pc] = *(const uint4*)(d_Xb + (size_t)(bm + r) * D + k0 + c * 8);
            Bv[r * 8 + pc] = *(const uint4*)(d_Yb + (size_t)(bn + r) * D + k0 + c * 8);
        }
        __syncthreads();

#pragma unroll
        for (int ks = 0; ks < BK / 16; ++ks) {
            uint32_t a[4][4], b[2][4];
#pragma unroll
            for (int mi = 0; mi < 4; ++mi) {
                int row = wm * 64 + mi * 16 + (lane & 15);
                int lc = ks * 2 + (lane >> 4);
                uint32_t addr = baseA + (uint32_t)(row * 8 + (lc ^ (row & 7))) * 16;
                asm volatile("ldmatrix.sync.aligned.m8n8.x4.shared.b16 {%0,%1,%2,%3},[%4];"
                             : "=r"(a[mi][0]), "=r"(a[mi][1]), "=r"(a[mi][2]), "=r"(a[mi][3])
                             : "r"(addr));
            }
#pragma unroll
            for (int nj = 0; nj < 2; ++nj) {
                int jrow = wn * 32 + nj * 16 + (lane & 7) + ((lane >> 3) & 1) * 8;
                int lc = ks * 2 + (lane >> 4);
                uint32_t addr = baseB + (uint32_t)(jrow * 8 + (lc ^ (jrow & 7))) * 16;
                asm volatile("ldmatrix.sync.aligned.m8n8.x4.shared.b16 {%0,%1,%2,%3},[%4];"
                             : "=r"(b[nj][0]), "=r"(b[nj][1]), "=r"(b[nj][2]), "=r"(b[nj][3])
                             : "r"(addr));
            }
#pragma unroll
            for (int mi = 0; mi < 4; ++mi)
#pragma unroll
                for (int ni = 0; ni < 4; ++ni) {
                    uint32_t b0 = b[ni >> 1][(ni & 1)];
                    uint32_t b1 = b[ni >> 1][(ni & 1) + 2];
                    asm volatile(
                        "mma.sync.aligned.m16n8k16.row.col.f32.bf16.bf16.f32 "
                        "{%0,%1,%2,%3},{%4,%5,%6,%7},{%8,%9},{%0,%1,%2,%3};"
                        : "+f"(acc[mi][ni][0]), "+f"(acc[mi][ni][1]),
                          "+f"(acc[mi][ni][2]), "+f"(acc[mi][ni][3])
                        : "r"(a[mi][0]), "r"(a[mi][1]), "r"(a[mi][2]), "r"(a[mi][3]),
                          "r"(b0), "r"(b1));
                }
        }
        __syncthreads();
    }

    int g = lane >> 2, t4 = lane & 3;
#pragma unroll
    for (int mi = 0; mi < 4; ++mi)
#pragma unroll
        for (int ni = 0; ni < 4; ++ni) {
            int col = wn * 32 + ni * 8 + t4 * 2;
            int r0 = wm * 64 + mi * 16 + g;
            __nv_bfloat162 p0 = __floats2bfloat162_rn(2.f * acc[mi][ni][0], 2.f * acc[mi][ni][1]);
            __nv_bfloat162 p1 = __floats2bfloat162_rn(2.f * acc[mi][ni][2], 2.f * acc[mi][ni][3]);
            *(__nv_bfloat162*)&Ct[r0 * 136 + col]       = p0;
            *(__nv_bfloat162*)&Ct[(r0 + 8) * 136 + col] = p1;
        }
    __syncthreads();

#pragma unroll
    for (int l = 0; l < 8; ++l) {
        int u = tid + l * 256;
        int r = u >> 4, q = u & 15;
        uint4 v = *(uint4*)&Ct[r * 136 + q * 8];
        *(uint4*)((__nv_bfloat16*)d_S + (size_t)(bm + r) * N + bn + q * 8) = v;
    }
    {
        int j = tid & 127, half = tid >> 7;
        int r0 = half * 64;
        __nv_bfloat16 hbuf[8];
#pragma unroll
        for (int seg = 0; seg < 8; ++seg) {
#pragma unroll
            for (int rr = 0; rr < 8; ++rr)
                hbuf[rr] = Ct[(r0 + seg * 8 + rr) * 136 + j];
            *(uint4*)((__nv_bfloat16*)d_St + (size_t)(bn + j) * N + bm + r0 + seg * 8)
                = *(uint4*)hbuf;
        }
    }
}

__device__ __forceinline__ void unpack8(uint4 u, float* v) {
    v[0] = __uint_as_float(u.x << 16);
    v[1] = __uint_as_float(u.x & 0xFFFF0000u);
    v[2] = __uint_as_float(u.y << 16);
    v[3] = __uint_as_float(u.y & 0xFFFF0000u);
    v[4] = __uint_as_float(u.z << 16);
    v[5] = __uint_as_float(u.z & 0xFFFF0000u);
    v[6] = __uint_as_float(u.w << 16);
    v[7] = __uint_as_float(u.w & 0xFFFF0000u);
}

/* ======= EXACT 2-pass LSE (seed iterations) ======= */
__global__ void __launch_bounds__(256) lse_kernel(const uint4* __restrict__ S,
                                                  const float* __restrict__ vh,
                                                  float* __restrict__ outh,
                                                  float* __restrict__ mrow,
                                                  float logw) {
    __shared__ float gs[N];
    __shared__ float redM[8];
    __shared__ float redS[8];
    int tid = threadIdx.x;
#pragma unroll
    for (int c = 0; c < 4; ++c)
        ((float4*)gs)[tid + c * 256] = ((const float4*)vh)[tid + c * 256];
    __syncthreads();
    int warp = tid >> 5, lane = tid & 31;

    for (int r = 0; r < RPB; ++r) {
        int row = blockIdx.x * RPB + r;
        const uint4* Sr = S + (size_t)row * (N / 8);
        float v[16];
        float lm = -1e30f;
#pragma unroll
        for (int c = 0; c < 2; ++c) {
            int idx = tid + c * 256;
            uint4 u = Sr[idx];
            float sv[8];
            unpack8(u, sv);
            float4 gA = ((const float4*)gs)[2 * idx];
            float4 gB = ((const float4*)gs)[2 * idx + 1];
            float* vv = v + c * 8;
            vv[0] = gA.x + sv[0]; vv[1] = gA.y + sv[1];
            vv[2] = gA.z + sv[2]; vv[3] = gA.w + sv[3];
            vv[4] = gB.x + sv[4]; vv[5] = gB.y + sv[5];
            vv[6] = gB.z + sv[6]; vv[7] = gB.w + sv[7];
#pragma unroll
            for (int k = 0; k < 8; k += 4)
                lm = fmaxf(lm, fmaxf(fmaxf(vv[k], vv[k + 1]),
                                     fmaxf(vv[k + 2], vv[k + 3])));
        }
#pragma unroll
        for (int o = 16; o; o >>= 1) lm = fmaxf(lm, __shfl_xor_sync(0xffffffffu, lm, o));
        if (lane == 0) redM[warp] = lm;
        __syncthreads();
        float m = redM[0];
#pragma unroll
        for (int k = 1; k < 8; ++k) m = fmaxf(m, redM[k]);

        float ls = 0.f;
#pragma unroll
        for (int k = 0; k < 16; ++k) {
            float dd = v[k] - m;
            if (dd > THRESH) ls += __expf(dd);
        }
#pragma unroll
        for (int o = 16; o; o >>= 1) ls += __shfl_xor_sync(0xffffffffu, ls, o);
        if (lane == 0) redS[warp] = ls;
        __syncthreads();
        if (tid == 0) {
            float s = redS[0];
#pragma unroll
            for (int k = 1; k < 8; ++k) s += redS[k];
            outh[row] = logw - (m + __logf(s));
            mrow[row] = m;
        }
        __syncthreads();
    }
}

/* ======= REBUILD: screened scan + candidate-list emission; resets barrier ==== */
__global__ void __launch_bounds__(256) lse_rebuild_kernel(const uint4* __restrict__ S,
                                                          const float* __restrict__ vh,
                                                          float* __restrict__ outh,
                                                          float* __restrict__ mrow,
                                                          unsigned short* __restrict__ idxl,
                                                          int* __restrict__ cntl,
                                                          float logw) {
    bar_reset(threadIdx.x, blockIdx.x);
    __shared__ float gsf[N];
    __shared__ __nv_bfloat162 gs2[N / 2];
    __shared__ int scnt[8];
    int tid = threadIdx.x;
#pragma unroll
    for (int c = 0; c < 4; ++c) {
        float4 v = ((const float4*)vh)[tid + c * 256];
        ((float4*)gsf)[tid + c * 256] = v;
        gs2[(tid + c * 256) * 2]     = __floats2bfloat162_rn(v.x, v.y);
        gs2[(tid + c * 256) * 2 + 1] = __floats2bfloat162_rn(v.z, v.w);
    }
    if (tid < 8) scnt[tid] = 0;
    __syncthreads();
    int warp = tid >> 5, lane = tid & 31;
    int row = blockIdx.x * 8 + warp;
    float shift = mrow[row];
    float hscreen = shift - 48.0f;
    float hemit   = shift - 45.0f;
    const uint4* Sr = S + (size_t)row * (N / 8);
    const uint4* G2 = (const uint4*)gs2;
    const float4* GF = (const float4*)gsf;
    unsigned short* Ir = idxl + (size_t)row * CAP;
    float ls = 0.f, wm = -1e30f;

#pragma unroll 4
    for (int c = 0; c < 16; ++c) {
        int idx = lane + 32 * c;
        uint4 u = Sr[idx];
        uint4 g = G2[idx];
        __nv_bfloat162 h0 = __hadd2(*(__nv_bfloat162*)&u.x, *(__nv_bfloat162*)&g.x);
        __nv_bfloat162 h1 = __hadd2(*(__nv_bfloat162*)&u.y, *(__nv_bfloat162*)&g.y);
        __nv_bfloat162 h2 = __hadd2(*(__nv_bfloat162*)&u.z, *(__nv_bfloat162*)&g.z);
        __nv_bfloat162 h3 = __hadd2(*(__nv_bfloat162*)&u.w, *(__nv_bfloat162*)&g.w);
        __nv_bfloat162 mm = __hmax2(__hmax2(h0, h1), __hmax2(h2, h3));
        float cm = fmaxf(__low2float(mm), __high2float(mm));
        if (cm > hscreen) {
            float sv[8], t[8];
            unpack8(u, sv);
            float4 gA = GF[2 * idx];
            float4 gB = GF[2 * idx + 1];
            t[0] = gA.x + sv[0]; t[1] = gA.y + sv[1];
            t[2] = gA.z + sv[2]; t[3] = gA.w + sv[3];
            t[4] = gB.x + sv[4]; t[5] = gB.y + sv[5];
            t[6] = gB.z + sv[6]; t[7] = gB.w + sv[7];
            unsigned m8 = 0;
#pragma unroll
            for (int k = 0; k < 8; ++k) {
                wm = fmaxf(wm, t[k]);
                ls += __expf(fminf(t[k] - shift, 60.f));
                m8 |= (t[k] > hemit) ? (1u << k) : 0u;
            }
            if (m8) {
                int ne = __popc(m8);
                int pos = atomicAdd(&scnt[warp], ne);
#pragma unroll
                for (int k = 0; k < 8; ++k) {
                    if ((m8 >> k) & 1u) {
                        if (pos < CAP) Ir[pos] = (unsigned short)(idx * 8 + k);
                        pos++;
                    }
                }
            }
        }
    }
#pragma unroll
    for (int o = 16; o; o >>= 1) {
        wm = fmaxf(wm, __shfl_xor_sync(0xffffffffu, wm, o));
        ls += __shfl_xor_sync(0xffffffffu, ls, o);
    }
    __syncwarp();
    if (lane == 0) {
        int c = scnt[warp]; if (c > CAP) c = CAP;
        cntl[row] = c;
        ls = fmaxf(ls, 1e-37f);
        outh[row] = logw - (shift + __logf(ls));
        mrow[row] = wm + 1.0f;
    }
}

/* ======= persistent sparse kernel with two-level barrier ======= */
__device__ __forceinline__ void grid_barrier(unsigned& k) {
    __syncthreads();
    if (threadIdx.x == 0) {
        __threadfence();
        unsigned b = blockIdx.x & 15u;
        if (atomicAdd(&d_bkt[b], 1u) == k * (PBLK / 16u) + (PBLK / 16u - 1u)) {
            if (atomicAdd(&d_master, 1u) == k * 16u + 15u) {
                __threadfence();
                d_gen = k + 1u;
            }
        }
        while (d_gen <= k) { }
        __threadfence();
    }
    __syncthreads();
    k++;
}

__device__ __forceinline__ void sparse_row(const __nv_bfloat16* __restrict__ S,
                                           const float* __restrict__ vh,
                                           float* __restrict__ outh,
                                           const unsigned short* __restrict__ idxl,
                                           int cnt, int row, float& shift,
                                           float logw, int lane) {
    const unsigned short* Ir = idxl + (size_t)row * CAP;
    const unsigned short* Sr = (const unsigned short*)S + (size_t)row * N;
    float ls = 0.f, wm = -1e30f;
    for (int e = lane; e < cnt; e += 32) {
        int j = __ldg(&Ir[e]);
        float v = __ldcg(&vh[j]) + bf16_raw_to_f(__ldg(&Sr[j]));
        wm = fmaxf(wm, v);
        ls += __expf(fminf(v - shift, 60.f));
    }
#pragma unroll
    for (int o = 16; o; o >>= 1) {
        wm = fmaxf(wm, __shfl_xor_sync(0xffffffffu, wm, o));
        ls += __shfl_xor_sync(0xffffffffu, ls, o);
    }
    ls = fmaxf(ls, 1e-37f);
    if (lane == 0) outh[row] = logw - (shift + __logf(ls));
    shift = wm + 1.0f;
}

__global__ void __launch_bounds__(256, 2) sparse_multi_kernel(
        const __nv_bfloat16* __restrict__ S, const __nv_bfloat16* __restrict__ St,
        float* __restrict__ fh, float* __restrict__ gh,
        float* __restrict__ mf, float* __restrict__ mg,
        const unsigned short* __restrict__ idxf, const int* __restrict__ cntf,
        const unsigned short* __restrict__ idxg, const int* __restrict__ cntg,
        int niter) {
    int tid = threadIdx.x, warp = tid >> 5, lane = tid & 31;
    int gw = blockIdx.x * 8 + warp;
    int r0 = gw, r1 = gw + 2048;
    float sf0 = mf[r0], sf1 = mf[r1];
    float sg0 = mg[r0], sg1 = mg[r1];
    int cf0 = cntf[r0], cf1 = cntf[r1];
    int cg0 = cntg[r0], cg1 = cntg[r1];
    unsigned bk = 0;

    for (int it = 0; it < niter; ++it) {
        sparse_row(S, gh, fh, idxf, cf0, r0, sf0, LA, lane);
        sparse_row(S, gh, fh, idxf, cf1, r1, sf1, LA, lane);
        grid_barrier(bk);
        sparse_row(St, fh, gh, idxg, cg0, r0, sg0, LB, lane);
        sparse_row(St, fh, gh, idxg, cg1, r1, sg1, LB, lane);
        grid_barrier(bk);
    }
    if (lane == 0) {
        mf[r0] = sf0; mf[r1] = sf1;
        mg[r0] = sg0; mg[r1] = sg1;
    }
}

/* ======= exact P row/col sums ======= */
__global__ void __launch_bounds__(256) psum_kernel(const uint4* __restrict__ S,
                                                   const float* __restrict__ vh,
                                                   const float* __restrict__ scalh,
                                                   float* __restrict__ outv) {
    __shared__ float gs[N];
    __shared__ float redS[8];
    int tid = threadIdx.x;
#pragma unroll
    for (int c = 0; c < 4; ++c)
        ((float4*)gs)[tid + c * 256] = ((const float4*)vh)[tid + c * 256];
    __syncthreads();
    int warp = tid >> 5, lane = tid & 31;

    for (int r = 0; r < RPB; ++r) {
        int row = blockIdx.x * RPB + r;
        float fr = scalh[row];
        const uint4* Sr = S + (size_t)row * (N / 8);
        float ls = 0.f;
#pragma unroll
        for (int c = 0; c < 2; ++c) {
            int idx = tid + c * 256;
            uint4 u = Sr[idx];
            float sv[8];
            unpack8(u, sv);
            float4 gA = ((const float4*)gs)[2 * idx];
            float4 gB = ((const float4*)gs)[2 * idx + 1];
            float t[8];
            t[0] = fr + gA.x + sv[0]; t[1] = fr + gA.y + sv[1];
            t[2] = fr + gA.z + sv[2]; t[3] = fr + gA.w + sv[3];
            t[4] = fr + gB.x + sv[4]; t[5] = fr + gB.y + sv[5];
            t[6] = fr + gB.z + sv[6]; t[7] = fr + gB.w + sv[7];
#pragma unroll
            for (int k = 0; k < 8; ++k)
                if (t[k] > THRESH_P) ls += __expf(t[k]);
        }
#pragma unroll
        for (int o = 16; o; o >>= 1) ls += __shfl_xor_sync(0xffffffffu, ls, o);
        if (lane == 0) redS[warp] = ls;
        __syncthreads();
        if (tid == 0) {
            float s = redS[0];
#pragma unroll
            for (int k = 1; k < 8; ++k) s += redS[k];
            outv[row] = s;
        }
        __syncthreads();
    }
}

__global__ void __launch_bounds__(256) final_kernel(float* __restrict__ out) {
    int tid = threadIdx.x;
    double acc = 0.0;
    const double k = (double)LA + (double)LB + 1.0;
    for (int i = tid; i < N; i += 256) {
        double Ri = (double)d_R[i];
        double fi = (double)d_fh[i] + (double)d_x2[i];
        double gi = (double)d_gh[i] + (double)d_y2[i];
        acc += fi * Ri + gi * (double)d_C[i] - k * Ri;
    }
    __shared__ double red[256];
    red[tid] = acc;
    __syncthreads();
    for (int o = 128; o; o >>= 1) {
        if (tid < o) red[tid] += red[tid + o];
        __syncthreads();
    }
    if (tid == 0) out[0] = (float)(red[0] + 1.0);
}

/* ================================================================= */
extern "C" void kernel_launch(void* const* d_in, const int* in_sizes, int n_in,
                              void* d_out, int out_size) {
    (void)in_sizes; (void)n_in; (void)out_size;
    const float* x = (const float*)d_in[0];
    const float* y = (const float*)d_in[1];
    float* out = (float*)d_out;

    void *pS_, *pSt_, *pfh_, *pgh_, *pmf_, *pmg_, *pR_, *pC_;
    void *pif_, *pig_, *pcf_, *pcg_;
    cudaGetSymbolAddress(&pS_,  d_S);
    cudaGetSymbolAddress(&pSt_, d_St);
    cudaGetSymbolAddress(&pfh_, d_fh);
    cudaGetSymbolAddress(&pgh_, d_gh);
    cudaGetSymbolAddress(&pmf_, d_mf);
    cudaGetSymbolAddress(&pmg_, d_mg);
    cudaGetSymbolAddress(&pR_,  d_R);
    cudaGetSymbolAddress(&pC_,  d_C);
    cudaGetSymbolAddress(&pif_, d_idxf);
    cudaGetSymbolAddress(&pig_, d_idxg);
    cudaGetSymbolAddress(&pcf_, d_cntf);
    cudaGetSymbolAddress(&pcg_, d_cntg);
    const uint4* pS  = (const uint4*)pS_;
    const uint4* pSt = (const uint4*)pSt_;
    const __nv_bfloat16* pSb  = (const __nv_bfloat16*)pS_;
    const __nv_bfloat16* pStb = (const __nv_bfloat16*)pSt_;
    float* pfh = (float*)pfh_;
    float* pgh = (float*)pgh_;
    float* pmf = (float*)pmf_;
    float* pmg = (float*)pmg_;
    float* pR  = (float*)pR_;
    float* pC  = (float*)pC_;
    unsigned short* pif = (unsigned short*)pif_;
    unsigned short* pig = (unsigned short*)pig_;
    int* pcf = (int*)pcf_;
    int* pcg = (int*)pcg_;

    prep_kernel<<<1024, 256>>>(x, y);
    gemm_tc_kernel<<<dim3(32, 32), 256>>>();

    /* 2 exact seed iterations */
    for (int it = 0; it < 2; ++it) {
        lse_kernel<<<N / RPB, 256>>>(pS,  pgh, pfh, pmf, LA);
        lse_kernel<<<N / RPB, 256>>>(pSt, pfh, pgh, pmg, LB);
    }

    /* rebuilds at {2,4,8,16,32,48,64,80,96}; persistent sparse between */
    const int segs[9] = {1, 3, 7, 15, 15, 15, 15, 15, 3};
    for (int s = 0; s < 9; ++s) {
        lse_rebuild_kernel<<<N / 8, 256>>>(pS,  pgh, pfh, pmf, pif, pcf, LA);
        lse_rebuild_kernel<<<N / 8, 256>>>(pSt, pfh, pgh, pmg, pig, pcg, LB);
        sparse_multi_kernel<<<PBLK, 256>>>(pSb, pStb, pfh, pgh, pmf, pmg,
                                           pif, pcf, pig, pcg, segs[s]);
    }

    psum_kernel<<<N / RPB, 256>>>(pS,  pgh, pfh, pR);
    psum_kernel<<<N / RPB, 256>>>(pSt, pfh, pgh, pC);
    final_kernel<<<1, 256>>>(out);
}